// round 16
// baseline (speedup 1.0000x reference)
#include <cuda_runtime.h>
#include <cuda_fp16.h>
#include <math.h>
#include <stdint.h>

#define NB 4
#define NC 512
#define NT 1024
#define NHEADS 8
#define NHD 64
#define EPS_IN 1e-5f
#define QT 32
#define CH 32

// ---------------- device scratch ----------------
__device__ __half g_w16[4 * NC * NC];
__device__ __half g_xT[NB * NT * NC];
__device__ __half g_qT[NB * NT * NC];
__device__ __half g_kT[NB * NT * NC];
__device__ __half g_vh[NB * NC * NT];
__device__ float g_opart[2 * NB * NHEADS * NT * NHD];      // partial O per T-half
__device__ float g_pm[2 * NB * NHEADS * NT];               // partial max (base-2)
__device__ float g_pl[2 * NB * NHEADS * NT];               // partial l
__device__ float g_ps2[2 * NB * NHEADS * NT];              // partial sum p^2
__device__ float g_c0[NB * NHEADS * NT];                   // alpha*w0/l per row
__device__ float g_c1[NB * NHEADS * NT];                   // alpha*w1/l per row
__device__ float g_vsum[NB * NC];
__device__ float g_betac[32];

__device__ __forceinline__ void mma16h(float* c, const uint32_t* a, const uint32_t* b) {
    asm volatile("mma.sync.aligned.m16n8k16.row.col.f32.f16.f16.f32 "
        "{%0,%1,%2,%3}, {%4,%5,%6,%7}, {%8,%9}, {%0,%1,%2,%3};\n"
        : "+f"(c[0]), "+f"(c[1]), "+f"(c[2]), "+f"(c[3])
        : "r"(a[0]), "r"(a[1]), "r"(a[2]), "r"(a[3]), "r"(b[0]), "r"(b[1]));
}
__device__ __forceinline__ float ex2f(float x) {
    float r;
    asm("ex2.approx.ftz.f32 %0, %1;" : "=f"(r) : "f"(x));
    return r;
}
__device__ __forceinline__ void ldsm4(uint32_t& r0, uint32_t& r1, uint32_t& r2, uint32_t& r3,
                                      uint32_t addr) {
    asm volatile("ldmatrix.sync.aligned.m8n8.x4.shared.b16 {%0,%1,%2,%3}, [%4];"
        : "=r"(r0), "=r"(r1), "=r"(r2), "=r"(r3) : "r"(addr));
}
__device__ __forceinline__ uint32_t hmul2u(uint32_t a, uint32_t w) {
    __half2 r = __hmul2(*(__half2*)&a, *(__half2*)&w);
    return *(uint32_t*)&r;
}

// ============ prep: weights -> fp16 ============
__global__ __launch_bounds__(256) void prep_w(const float* __restrict__ wq,
                                              const float* __restrict__ wk,
                                              const float* __restrict__ wv,
                                              const float* __restrict__ wp) {
    int idx = blockIdx.x * 256 + threadIdx.x;
    int which = idx >> 18, off = idx & 262143;
    const float* s = (which == 0) ? wq : (which == 1) ? wk : (which == 2) ? wv : wp;
    g_w16[idx] = __float2half(s[off]);
}

// ============ prep: xT[b][t][c] fp16 ============
__global__ __launch_bounds__(256) void prep_x(const float* __restrict__ x) {
    __shared__ float tile[32][33];
    int tx = threadIdx.x, ty = threadIdx.y;
    int tBase = blockIdx.x * 32, cBase = blockIdx.y * 32, b = blockIdx.z;
    const float* X = x + (size_t)b * NC * NT;
#pragma unroll
    for (int p = 0; p < 4; p++)
        tile[ty + 8 * p][tx] = X[(size_t)(cBase + ty + 8 * p) * NT + tBase + tx];
    __syncthreads();
    __half* dst = g_xT + (size_t)b * NT * NC;
#pragma unroll
    for (int p = 0; p < 4; p++)
        dst[(size_t)(tBase + ty + 8 * p) * NC + cBase + tx] = __float2half(tile[tx][ty + 8 * p]);
}

// ============ Kernel 1: QKV fp16 ============
__global__ __launch_bounds__(256) void qkv_f16() {
    int z = blockIdx.z;
    int b = z / 3, which = z - b * 3;
    const __half* W = g_w16 + (size_t)which * NC * NC;
    const __half* X = g_xT + (size_t)b * NT * NC;

    int oBase = blockIdx.y * 128;
    int tBase = blockIdx.x * 128;

    __shared__ union {
        struct { uint32_t A[128][20]; uint32_t B[128][20]; } ab;
        unsigned short st[128][136];
    } smu;

    int tid = threadIdx.x, lane = tid & 31, wid = tid >> 5;
    int wm = wid >> 2, wn = wid & 3;
    int lr = lane >> 2, lk = lane & 3;

    float acc[4][4][4];
#pragma unroll
    for (int mi = 0; mi < 4; mi++)
#pragma unroll
        for (int nj = 0; nj < 4; nj++)
#pragma unroll
            for (int ci = 0; ci < 4; ci++) acc[mi][nj][ci] = 0.f;

    for (int k0 = 0; k0 < NC; k0 += 32) {
#pragma unroll
        for (int i = 0; i < 2; i++) {
            int idx = tid + i * 256;
            int row = idx >> 2, uu = idx & 3;
            *(uint4*)&smu.ab.A[row][uu * 4] =
                *(const uint4*)&W[(size_t)(oBase + row) * NC + k0 + uu * 8];
            *(uint4*)&smu.ab.B[row][uu * 4] =
                *(const uint4*)&X[(size_t)(tBase + row) * NC + k0 + uu * 8];
        }
        __syncthreads();
#pragma unroll
        for (int ci = 0; ci < 2; ci++) {
            int kc = ci * 8;
            uint32_t af[4][4], bf[4][2];
#pragma unroll
            for (int mi = 0; mi < 4; mi++) {
                int m0 = wm * 64 + mi * 16 + lr;
                af[mi][0] = smu.ab.A[m0][kc + lk];
                af[mi][1] = smu.ab.A[m0 + 8][kc + lk];
                af[mi][2] = smu.ab.A[m0][kc + lk + 4];
                af[mi][3] = smu.ab.A[m0 + 8][kc + lk + 4];
            }
#pragma unroll
            for (int nj = 0; nj < 4; nj++) {
                int n0 = wn * 32 + nj * 8 + lr;
                bf[nj][0] = smu.ab.B[n0][kc + lk];
                bf[nj][1] = smu.ab.B[n0][kc + lk + 4];
            }
#pragma unroll
            for (int mi = 0; mi < 4; mi++)
#pragma unroll
                for (int nj = 0; nj < 4; nj++) mma16h(acc[mi][nj], af[mi], bf[nj]);
        }
        __syncthreads();
    }

    if (which == 2) {
        __half* vh = g_vh + (size_t)b * NC * NT;
#pragma unroll
        for (int mi = 0; mi < 4; mi++) {
            int r = oBase + wm * 64 + mi * 16 + lr;
#pragma unroll
            for (int nj = 0; nj < 4; nj++) {
                int cc = tBase + wn * 32 + nj * 8 + lk * 2;
                *(__half2*)&vh[(size_t)r * NT + cc] =
                    __floats2half2_rn(acc[mi][nj][0], acc[mi][nj][1]);
                *(__half2*)&vh[(size_t)(r + 8) * NT + cc] =
                    __floats2half2_rn(acc[mi][nj][2], acc[mi][nj][3]);
            }
        }
    } else {
        __half* dst = ((which == 0) ? g_qT : g_kT) + (size_t)b * NT * NC;
#pragma unroll
        for (int mi = 0; mi < 4; mi++) {
            int r = wm * 64 + mi * 16 + lr;
#pragma unroll
            for (int nj = 0; nj < 4; nj++) {
                int cc = wn * 32 + nj * 8 + lk * 2;
                smu.st[cc][r]         = __half_as_ushort(__float2half(acc[mi][nj][0]));
                smu.st[cc + 1][r]     = __half_as_ushort(__float2half(acc[mi][nj][1]));
                smu.st[cc][r + 8]     = __half_as_ushort(__float2half(acc[mi][nj][2]));
                smu.st[cc + 1][r + 8] = __half_as_ushort(__float2half(acc[mi][nj][3]));
            }
        }
        __syncthreads();
        int row = tid >> 1, ub = (tid & 1) * 8;
#pragma unroll
        for (int j = 0; j < 8; j++) {
            *(uint4*)&dst[(size_t)(tBase + row) * NC + oBase + (ub + j) * 8] =
                *(const uint4*)&smu.st[row][(ub + j) * 8];
        }
    }
}

// ============ Kernel 2: fused attention — mix folded into QK mma (K=512), S/P in registers ============
// Warp g owns group g's full 32q stripe. smem: Q [32q][520]h | K [32t][520]h / V [512][40]h overlay.
__global__ __launch_bounds__(256, 2) void fa5(const float* __restrict__ w_head) {
    extern __shared__ char smc[];
    __half* QsH = (__half*)smc;                        // 32*520*2 = 33280
    __half* KVH = (__half*)(smc + 33280);              // K 33280 / V 40960

    int b = blockIdx.y;
    int qBase = (blockIdx.x >> 1) * QT;
    int part = blockIdx.x & 1;
    int tid = threadIdx.x, lane = tid & 31, g = tid >> 5;
    int lr = lane >> 2, lk = lane & 3;

    // per-warp mix weights (log2e and 0.125 folded), fp16 broadcast pairs
    uint32_t wh2[8];
#pragma unroll
    for (int h = 0; h < 8; h++) {
        __half2 w = __float2half2_rn(w_head[g * 8 + h] * 1.4426950408889634f * 0.125f);
        wh2[h] = *(uint32_t*)&w;
    }

    // ldmatrix lane addresses
    uint32_t aQ = (uint32_t)__cvta_generic_to_shared(
        QsH + (lane & 15) * 520 + ((lane >> 4) << 3));
    uint32_t bK = (uint32_t)__cvta_generic_to_shared(
        KVH + (((lane >> 4) << 3) + (lane & 7)) * 520 + (((lane >> 3) & 1) << 3));
    uint32_t bV = (uint32_t)__cvta_generic_to_shared(
        KVH + (((lane >> 4) << 3) + (lane & 7)) * 40 + (((lane >> 3) & 1) << 3));

    // stage Q [32q][520]
    {
        const __half* Qsrc = g_qT + ((size_t)b * NT + qBase) * NC;
#pragma unroll
        for (int i = 0; i < 8; i++) {
            int idx = tid + i * 256;
            int q = idx >> 6, u = idx & 63;
            *(uint4*)&QsH[q * 520 + u * 8] = *(const uint4*)&Qsrc[q * NC + u * 8];
        }
    }

    // online stats per row-slot: [mi][half] -> rows mi*16+lr, mi*16+lr+8
    float m[2][2], l[2][2], s2[2][2];
#pragma unroll
    for (int mi = 0; mi < 2; mi++)
#pragma unroll
        for (int hf = 0; hf < 2; hf++) { m[mi][hf] = -1e30f; l[mi][hf] = 0.f; s2[mi][hf] = 0.f; }

    float pv[2][8][4];
#pragma unroll
    for (int mi = 0; mi < 2; mi++)
#pragma unroll
        for (int nj = 0; nj < 8; nj++)
#pragma unroll
            for (int ci = 0; ci < 4; ci++) pv[mi][nj][ci] = 0.f;

    const __half* Ksrc = g_kT + (size_t)b * NT * NC;
    const __half* Vsrc = g_vh + (size_t)b * NC * NT;
    int tPart = part * 512;

    __syncthreads();

    for (int cc0 = 0; cc0 < 512; cc0 += CH) {
        int c0 = tPart + cc0;
        // ---- stage K [32t][520] ----
#pragma unroll
        for (int i = 0; i < 8; i++) {
            int idx = tid + i * 256;
            int t = idx >> 6, u = idx & 63;
            *(uint4*)&KVH[t * 520 + u * 8] =
                *(const uint4*)&Ksrc[(size_t)(c0 + t) * NC + u * 8];
        }
        __syncthreads();

        // ---- S: warp g computes mixed logits [32q][32t] directly, K=512, w folded into A ----
        float sacc[2][4][4];
#pragma unroll
        for (int mi = 0; mi < 2; mi++)
#pragma unroll
            for (int nj = 0; nj < 4; nj++)
#pragma unroll
                for (int ci = 0; ci < 4; ci++) sacc[mi][nj][ci] = 0.f;
#pragma unroll
        for (int ks = 0; ks < 32; ks++) {
            int h = ks >> 2;
            uint32_t w2 = wh2[h];
            uint32_t af[2][4], bf[4][2];
#pragma unroll
            for (int mi = 0; mi < 2; mi++) {
                ldsm4(af[mi][0], af[mi][1], af[mi][2], af[mi][3],
                      aQ + (mi * 16 * 520 + ks * 16) * 2);
                af[mi][0] = hmul2u(af[mi][0], w2);
                af[mi][1] = hmul2u(af[mi][1], w2);
                af[mi][2] = hmul2u(af[mi][2], w2);
                af[mi][3] = hmul2u(af[mi][3], w2);
            }
#pragma unroll
            for (int j = 0; j < 2; j++) {
                uint32_t r0, r1, r2, r3;
                ldsm4(r0, r1, r2, r3, bK + (j * 16 * 520 + ks * 16) * 2);
                bf[j * 2][0] = r0; bf[j * 2][1] = r1;
                bf[j * 2 + 1][0] = r2; bf[j * 2 + 1][1] = r3;
            }
#pragma unroll
            for (int mi = 0; mi < 2; mi++)
#pragma unroll
                for (int nj = 0; nj < 4; nj++) mma16h(sacc[mi][nj], af[mi], bf[nj]);
        }
        __syncthreads();   // K reads done; V may overwrite

        // ---- softmax in registers; sacc becomes p ----
        float sc[2][2];
#pragma unroll
        for (int mi = 0; mi < 2; mi++) {
#pragma unroll
            for (int hf = 0; hf < 2; hf++) {
                int ci0 = hf * 2;
                float cm = fmaxf(fmaxf(sacc[mi][0][ci0], sacc[mi][0][ci0 + 1]),
                                 fmaxf(sacc[mi][1][ci0], sacc[mi][1][ci0 + 1]));
                cm = fmaxf(cm, fmaxf(fmaxf(sacc[mi][2][ci0], sacc[mi][2][ci0 + 1]),
                                     fmaxf(sacc[mi][3][ci0], sacc[mi][3][ci0 + 1])));
                cm = fmaxf(cm, __shfl_xor_sync(0xffffffffu, cm, 1));
                cm = fmaxf(cm, __shfl_xor_sync(0xffffffffu, cm, 2));
                float nm = fmaxf(m[mi][hf], cm);
                float rs = ex2f(m[mi][hf] - nm);
                m[mi][hf] = nm;
                sc[mi][hf] = rs;
                float cl = 0.f, cq = 0.f;
#pragma unroll
                for (int nj = 0; nj < 4; nj++) {
                    float p0 = ex2f(sacc[mi][nj][ci0] - nm);
                    float p1 = ex2f(sacc[mi][nj][ci0 + 1] - nm);
                    sacc[mi][nj][ci0] = p0;
                    sacc[mi][nj][ci0 + 1] = p1;
                    cl += p0 + p1;
                    cq += p0 * p0 + p1 * p1;
                }
                cl += __shfl_xor_sync(0xffffffffu, cl, 1);
                cq += __shfl_xor_sync(0xffffffffu, cq, 1);
                cl += __shfl_xor_sync(0xffffffffu, cl, 2);
                cq += __shfl_xor_sync(0xffffffffu, cq, 2);
                l[mi][hf] = l[mi][hf] * rs + cl;
                s2[mi][hf] = s2[mi][hf] * (rs * rs) + cq;
            }
        }

        // ---- P fragments from registers (C-layout -> A-layout) ----
        uint32_t pf[2][2][4];   // [mi][kt][4]
#pragma unroll
        for (int mi = 0; mi < 2; mi++)
#pragma unroll
            for (int kt = 0; kt < 2; kt++) {
                __half2 h0 = __floats2half2_rn(sacc[mi][2 * kt][0], sacc[mi][2 * kt][1]);
                __half2 h1 = __floats2half2_rn(sacc[mi][2 * kt][2], sacc[mi][2 * kt][3]);
                __half2 h2 = __floats2half2_rn(sacc[mi][2 * kt + 1][0], sacc[mi][2 * kt + 1][1]);
                __half2 h3 = __floats2half2_rn(sacc[mi][2 * kt + 1][2], sacc[mi][2 * kt + 1][3]);
                pf[mi][kt][0] = *(uint32_t*)&h0;
                pf[mi][kt][1] = *(uint32_t*)&h1;
                pf[mi][kt][2] = *(uint32_t*)&h2;
                pf[mi][kt][3] = *(uint32_t*)&h3;
            }

        // ---- stage V [512c][40t] over K region ----
#pragma unroll
        for (int i = 0; i < 8; i++) {
            int idx = tid + i * 256;
            int c = idx >> 2, seg = idx & 3;
            *(uint4*)&KVH[c * 40 + seg * 8] =
                *(const uint4*)&Vsrc[(size_t)c * NT + c0 + seg * 8];
        }
        __syncthreads();

        // ---- rescale pv, then PV mma ----
#pragma unroll
        for (int mi = 0; mi < 2; mi++)
#pragma unroll
            for (int nj = 0; nj < 8; nj++) {
                pv[mi][nj][0] *= sc[mi][0]; pv[mi][nj][1] *= sc[mi][0];
                pv[mi][nj][2] *= sc[mi][1]; pv[mi][nj][3] *= sc[mi][1];
            }
#pragma unroll
        for (int kt = 0; kt < 2; kt++) {
#pragma unroll
            for (int j = 0; j < 4; j++) {
                uint32_t r0, r1, r2, r3;
                ldsm4(r0, r1, r2, r3, bV + ((g * 64 + j * 16) * 40 + kt * 16) * 2);
                uint32_t bf0[2] = {r0, r1}, bf1[2] = {r2, r3};
#pragma unroll
                for (int mi = 0; mi < 2; mi++) {
                    mma16h(pv[mi][j * 2], pf[mi][kt], bf0);
                    mma16h(pv[mi][j * 2 + 1], pf[mi][kt], bf1);
                }
            }
        }
        __syncthreads();   // V reads done; next K stage may overwrite
    }

    // ---- epilogue: stats + partial O ----
    if (lk == 0) {
#pragma unroll
        for (int mi = 0; mi < 2; mi++)
#pragma unroll
            for (int hf = 0; hf < 2; hf++) {
                int row = mi * 16 + hf * 8 + lr;
                int r = (b * 8 + g) * NT + qBase + row;
                int pr = part * 32768 + r;
                g_pm[pr] = m[mi][hf];
                g_pl[pr] = l[mi][hf];
                g_ps2[pr] = s2[mi][hf];
            }
    }
    {
        float* Op = g_opart + ((size_t)(part * 32 + b * 8 + g) * NT + qBase) * NHD;
#pragma unroll
        for (int mi = 0; mi < 2; mi++) {
            int r0 = mi * 16 + lr;
#pragma unroll
            for (int nj = 0; nj < 8; nj++) {
                int cc = nj * 8 + lk * 2;
                *(float2*)&Op[(size_t)r0 * NHD + cc] = make_float2(pv[mi][nj][0], pv[mi][nj][1]);
                *(float2*)&Op[(size_t)(r0 + 8) * NHD + cc] = make_float2(pv[mi][nj][2], pv[mi][nj][3]);
            }
        }
    }
}

// ============ Kernel 4: vsum — one warp per row, MLP 4 ============
__global__ __launch_bounds__(256) void vsum2() {
    int wid = threadIdx.x >> 5, lane = threadIdx.x & 31;
    int row = blockIdx.x * 8 + wid;
    const uint4* p = (const uint4*)(g_vh + (size_t)row * NT);
    uint4 u0 = p[lane], u1 = p[lane + 32], u2 = p[lane + 64], u3 = p[lane + 96];
    float s = 0.f;
#pragma unroll
    for (int k = 0; k < 4; k++) {
        uint4 u = (k == 0) ? u0 : (k == 1) ? u1 : (k == 2) ? u2 : u3;
        const __half2* h2 = (const __half2*)&u;
#pragma unroll
        for (int j = 0; j < 4; j++) {
            float2 f = __half22float2(h2[j]);
            s += f.x + f.y;
        }
    }
#pragma unroll
    for (int o = 16; o > 0; o >>= 1) s += __shfl_xor_sync(0xffffffffu, s, o);
    if (lane == 0) g_vsum[row] = s;
}

// ============ Kernel 5: finalize — InstanceNorm params + per-row combine coeffs ============
__global__ __launch_bounds__(256) void finalize2(const float* __restrict__ gamma,
                                                 const float* __restrict__ beta) {
    __shared__ float sbuf[8];
    __shared__ float sAlpha;
    int grp = blockIdx.x;
    float sum = 0.f;
    for (int i = threadIdx.x; i < NT; i += 256) {
        int r = grp * NT + i;
        float m0 = g_pm[r], m1 = g_pm[32768 + r];
        float mx = fmaxf(m0, m1);
        float w0 = ex2f(m0 - mx), w1 = ex2f(m1 - mx);
        float lv = g_pl[r] * w0 + g_pl[32768 + r] * w1;
        float sv = g_ps2[r] * (w0 * w0) + g_ps2[32768 + r] * (w1 * w1);
        sum += sv / (lv * lv);
    }
    int lane = threadIdx.x & 31, w = threadIdx.x >> 5;
#pragma unroll
    for (int o = 16; o > 0; o >>= 1) sum += __shfl_xor_sync(0xffffffffu, sum, o);
    if (lane == 0) sbuf[w] = sum;
    __syncthreads();
    if (threadIdx.x == 0) {
        float sumsq = 0.f;
        for (int i = 0; i < 8; i++) sumsq += sbuf[i];
        const float invN = 1.f / (1024.f * 1024.f);
        float mean = 1.f / 1024.f;
        float var = sumsq * invN - mean * mean;
        int h = grp & 7;
        float alpha = gamma[h] * rsqrtf(var + EPS_IN);
        sAlpha = alpha;
        g_betac[grp] = beta[h] - alpha * mean;
    }
    __syncthreads();
    float alpha = sAlpha;
    for (int i = threadIdx.x; i < NT; i += 256) {
        int r = grp * NT + i;
        float m0 = g_pm[r], m1 = g_pm[32768 + r];
        float mx = fmaxf(m0, m1);
        float w0 = ex2f(m0 - mx), w1 = ex2f(m1 - mx);
        float lv = g_pl[r] * w0 + g_pl[32768 + r] * w1;
        float ai = alpha / lv;
        g_c0[r] = ai * w0;
        g_c1[r] = ai * w1;
    }
}

// ============ Kernel 6: projection, fused partial-combine + normalize on load ============
__global__ __launch_bounds__(256) void proj_fused(const float* __restrict__ b_proj,
                                                  float* __restrict__ outF) {
    int b = blockIdx.z;
    int coBase = blockIdx.y * 128;
    int tBase = blockIdx.x * 128;
    const __half* W = g_w16 + (size_t)3 * NC * NC;

    __shared__ uint32_t As[128][20];
    __shared__ uint32_t Bs[128][20];

    int tid = threadIdx.x, lane = tid & 31, wid = tid >> 5;
    int wm = wid >> 2, wn = wid & 3;
    int lr = lane >> 2, lk = lane & 3;

    float acc[4][4][4];
#pragma unroll
    for (int mi = 0; mi < 4; mi++)
#pragma unroll
        for (int nj = 0; nj < 4; nj++)
#pragma unroll
            for (int ci = 0; ci < 4; ci++) acc[mi][nj][ci] = 0.f;

    for (int k0 = 0; k0 < NC; k0 += 32) {
        int chi = k0 >> 6;
        int dBase = k0 & 63;
#pragma unroll
        for (int i = 0; i < 2; i++) {
            int idx = tid + i * 256;
            int row = idx >> 2, uu = idx & 3;
            *(uint4*)&As[row][uu * 4] =
                *(const uint4*)&W[(size_t)(coBase + row) * NC + k0 + uu * 8];
            int t = tBase + row;
            int bh = b * 8 + (t >> 7);
            int q  = ((t & 127) << 3) + chi;
            int d0 = dBase + uu * 8;
            int r = bh * NT + q;
            float c0 = g_c0[r], c1 = g_c1[r];
            float bc = g_betac[bh];
            const float* Op0 = &g_opart[((size_t)bh * NT + q) * NHD + d0];
            const float* Op1 = Op0 + 2097152;
            float4 p00 = *(const float4*)Op0;
            float4 p01 = *(const float4*)(Op0 + 4);
            float4 p10 = *(const float4*)Op1;
            float4 p11 = *(const float4*)(Op1 + 4);
            float4 v0 = *(const float4*)&g_vsum[bh * NHD + d0];
            float4 v1 = *(const float4*)&g_vsum[bh * NHD + d0 + 4];
            __half2 h0 = __floats2half2_rn(p00.x * c0 + p10.x * c1 + bc * v0.x,
                                           p00.y * c0 + p10.y * c1 + bc * v0.y);
            __half2 h1 = __floats2half2_rn(p00.z * c0 + p10.z * c1 + bc * v0.z,
                                           p00.w * c0 + p10.w * c1 + bc * v0.w);
            __half2 h2 = __floats2half2_rn(p01.x * c0 + p11.x * c1 + bc * v1.x,
                                           p01.y * c0 + p11.y * c1 + bc * v1.y);
            __half2 h3 = __floats2half2_rn(p01.z * c0 + p11.z * c1 + bc * v1.z,
                                           p01.w * c0 + p11.w * c1 + bc * v1.w);
            uint4 u;
            u.x = *(uint32_t*)&h0; u.y = *(uint32_t*)&h1;
            u.z = *(uint32_t*)&h2; u.w = *(uint32_t*)&h3;
            *(uint4*)&Bs[row][uu * 4] = u;
        }
        __syncthreads();
#pragma unroll
        for (int ci = 0; ci < 2; ci++) {
            int kc = ci * 8;
            uint32_t af[4][4], bf[4][2];
#pragma unroll
            for (int mi = 0; mi < 4; mi++) {
                int m0 = wm * 64 + mi * 16 + lr;
                af[mi][0] = As[m0][kc + lk];
                af[mi][1] = As[m0 + 8][kc + lk];
                af[mi][2] = As[m0][kc + lk + 4];
                af[mi][3] = As[m0 + 8][kc + lk + 4];
            }
#pragma unroll
            for (int nj = 0; nj < 4; nj++) {
                int n0 = wn * 32 + nj * 8 + lr;
                bf[nj][0] = Bs[n0][kc + lk];
                bf[nj][1] = Bs[n0][kc + lk + 4];
            }
#pragma unroll
            for (int mi = 0; mi < 4; mi++)
#pragma unroll
                for (int nj = 0; nj < 4; nj++) mma16h(acc[mi][nj], af[mi], bf[nj]);
        }
        __syncthreads();
    }
#pragma unroll
    for (int mi = 0; mi < 4; mi++) {
        int co = coBase + wm * 64 + mi * 16 + lr;
        float bias0 = b_proj[co], bias1 = b_proj[co + 8];
        float* op0 = outF + (size_t)b * NC * NT + (size_t)co * NT;
        float* op1 = op0 + (size_t)8 * NT;
#pragma unroll
        for (int nj = 0; nj < 4; nj++) {
            int cc = tBase + wn * 32 + nj * 8 + lk * 2;
            *(float2*)&op0[cc] = make_float2(acc[mi][nj][0] + bias0, acc[mi][nj][1] + bias0);
            *(float2*)&op1[cc] = make_float2(acc[mi][nj][2] + bias1, acc[mi][nj][3] + bias1);
        }
    }
}

// ---------------- launch ----------------
extern "C" void kernel_launch(void* const* d_in, const int* in_sizes, int n_in,
                              void* d_out, int out_size) {
    (void)in_sizes; (void)n_in; (void)out_size;
    const float* x        = (const float*)d_in[0];
    const float* w_q      = (const float*)d_in[1];
    const float* w_k      = (const float*)d_in[2];
    const float* w_v      = (const float*)d_in[3];
    const float* w_head   = (const float*)d_in[4];
    const float* in_gamma = (const float*)d_in[5];
    const float* in_beta  = (const float*)d_in[6];
    const float* w_proj   = (const float*)d_in[7];
    const float* b_proj   = (const float*)d_in[8];
    float* outF = (float*)d_out;

    const int FA_SMEM = 33280 + 40960;   // 74240
    cudaFuncSetAttribute(fa5, cudaFuncAttributeMaxDynamicSharedMemorySize, FA_SMEM);

    prep_w<<<4096, 256>>>(w_q, w_k, w_v, w_proj);
    prep_x<<<dim3(32, 16, 4), dim3(32, 8)>>>(x);
    qkv_f16<<<dim3(8, 4, 12), 256>>>();
    fa5<<<dim3(64, 4), 256, FA_SMEM>>>(w_head);           // 4th launch -> ncu target
    vsum2<<<256, 256>>>();
    finalize2<<<32, 256>>>(in_gamma, in_beta);
    proj_fused<<<dim3(8, 4, 4), 256>>>(b_proj, outF);
}

// round 17
// speedup vs baseline: 1.2437x; 1.2437x over previous
#include <cuda_runtime.h>
#include <cuda_fp16.h>
#include <math.h>
#include <stdint.h>

#define NB 4
#define NC 512
#define NT 1024
#define NHEADS 8
#define NHD 64
#define EPS_IN 1e-5f
#define QT 32
#define CH 64

// ---------------- device scratch ----------------
__device__ __half g_w16[4 * NC * NC];
__device__ __half g_xT[NB * NT * NC];
__device__ __half g_qT[NB * NT * NC];
__device__ __half g_kT[NB * NT * NC];
__device__ __half g_vh[NB * NC * NT];
__device__ float g_oacc[NB * NHEADS * NT * NHD];           // unnormalized PV accum [bh][q][d]
__device__ float g_l[NB * NHEADS * NT];
__device__ float g_rowsq[NB * NHEADS * NT];
__device__ float g_vsum[NB * NC];
__device__ float g_alpha[32];
__device__ float g_betac[32];

__device__ __forceinline__ void mma16h(float* c, const uint32_t* a, const uint32_t* b) {
    asm volatile("mma.sync.aligned.m16n8k16.row.col.f32.f16.f16.f32 "
        "{%0,%1,%2,%3}, {%4,%5,%6,%7}, {%8,%9}, {%0,%1,%2,%3};\n"
        : "+f"(c[0]), "+f"(c[1]), "+f"(c[2]), "+f"(c[3])
        : "r"(a[0]), "r"(a[1]), "r"(a[2]), "r"(a[3]), "r"(b[0]), "r"(b[1]));
}
__device__ __forceinline__ float ex2f(float x) {
    float r;
    asm("ex2.approx.ftz.f32 %0, %1;" : "=f"(r) : "f"(x));
    return r;
}

// ============ prep: weights -> fp16 ============
__global__ __launch_bounds__(256) void prep_w(const float* __restrict__ wq,
                                              const float* __restrict__ wk,
                                              const float* __restrict__ wv,
                                              const float* __restrict__ wp) {
    int idx = blockIdx.x * 256 + threadIdx.x;
    int which = idx >> 18, off = idx & 262143;
    const float* s = (which == 0) ? wq : (which == 1) ? wk : (which == 2) ? wv : wp;
    g_w16[idx] = __float2half(s[off]);
}

// ============ prep: xT[b][t][c] fp16 ============
__global__ __launch_bounds__(256) void prep_x(const float* __restrict__ x) {
    __shared__ float tile[32][33];
    int tx = threadIdx.x, ty = threadIdx.y;
    int tBase = blockIdx.x * 32, cBase = blockIdx.y * 32, b = blockIdx.z;
    const float* X = x + (size_t)b * NC * NT;
#pragma unroll
    for (int p = 0; p < 4; p++)
        tile[ty + 8 * p][tx] = X[(size_t)(cBase + ty + 8 * p) * NT + tBase + tx];
    __syncthreads();
    __half* dst = g_xT + (size_t)b * NT * NC;
#pragma unroll
    for (int p = 0; p < 4; p++)
        dst[(size_t)(tBase + ty + 8 * p) * NC + cBase + tx] = __float2half(tile[tx][ty + 8 * p]);
}

// ============ Kernel 1: QKV fp16 ============
__global__ __launch_bounds__(256) void qkv_f16() {
    int z = blockIdx.z;
    int b = z / 3, which = z - b * 3;
    const __half* W = g_w16 + (size_t)which * NC * NC;
    const __half* X = g_xT + (size_t)b * NT * NC;

    int oBase = blockIdx.y * 128;
    int tBase = blockIdx.x * 128;

    __shared__ union {
        struct { uint32_t A[128][20]; uint32_t B[128][20]; } ab;
        unsigned short st[128][136];
    } smu;

    int tid = threadIdx.x, lane = tid & 31, wid = tid >> 5;
    int wm = wid >> 2, wn = wid & 3;
    int lr = lane >> 2, lk = lane & 3;

    float acc[4][4][4];
#pragma unroll
    for (int mi = 0; mi < 4; mi++)
#pragma unroll
        for (int nj = 0; nj < 4; nj++)
#pragma unroll
            for (int ci = 0; ci < 4; ci++) acc[mi][nj][ci] = 0.f;

    for (int k0 = 0; k0 < NC; k0 += 32) {
#pragma unroll
        for (int i = 0; i < 2; i++) {
            int idx = tid + i * 256;
            int row = idx >> 2, uu = idx & 3;
            *(uint4*)&smu.ab.A[row][uu * 4] =
                *(const uint4*)&W[(size_t)(oBase + row) * NC + k0 + uu * 8];
            *(uint4*)&smu.ab.B[row][uu * 4] =
                *(const uint4*)&X[(size_t)(tBase + row) * NC + k0 + uu * 8];
        }
        __syncthreads();
#pragma unroll
        for (int ci = 0; ci < 2; ci++) {
            int kc = ci * 8;
            uint32_t af[4][4], bf[4][2];
#pragma unroll
            for (int mi = 0; mi < 4; mi++) {
                int m0 = wm * 64 + mi * 16 + lr;
                af[mi][0] = smu.ab.A[m0][kc + lk];
                af[mi][1] = smu.ab.A[m0 + 8][kc + lk];
                af[mi][2] = smu.ab.A[m0][kc + lk + 4];
                af[mi][3] = smu.ab.A[m0 + 8][kc + lk + 4];
            }
#pragma unroll
            for (int nj = 0; nj < 4; nj++) {
                int n0 = wn * 32 + nj * 8 + lr;
                bf[nj][0] = smu.ab.B[n0][kc + lk];
                bf[nj][1] = smu.ab.B[n0][kc + lk + 4];
            }
#pragma unroll
            for (int mi = 0; mi < 4; mi++)
#pragma unroll
                for (int nj = 0; nj < 4; nj++) mma16h(acc[mi][nj], af[mi], bf[nj]);
        }
        __syncthreads();
    }

    if (which == 2) {
        __half* vh = g_vh + (size_t)b * NC * NT;
#pragma unroll
        for (int mi = 0; mi < 4; mi++) {
            int r = oBase + wm * 64 + mi * 16 + lr;
#pragma unroll
            for (int nj = 0; nj < 4; nj++) {
                int cc = tBase + wn * 32 + nj * 8 + lk * 2;
                *(__half2*)&vh[(size_t)r * NT + cc] =
                    __floats2half2_rn(acc[mi][nj][0], acc[mi][nj][1]);
                *(__half2*)&vh[(size_t)(r + 8) * NT + cc] =
                    __floats2half2_rn(acc[mi][nj][2], acc[mi][nj][3]);
            }
        }
    } else {
        __half* dst = ((which == 0) ? g_qT : g_kT) + (size_t)b * NT * NC;
#pragma unroll
        for (int mi = 0; mi < 4; mi++) {
            int r = wm * 64 + mi * 16 + lr;
#pragma unroll
            for (int nj = 0; nj < 4; nj++) {
                int cc = wn * 32 + nj * 8 + lk * 2;
                smu.st[cc][r]         = __half_as_ushort(__float2half(acc[mi][nj][0]));
                smu.st[cc + 1][r]     = __half_as_ushort(__float2half(acc[mi][nj][1]));
                smu.st[cc][r + 8]     = __half_as_ushort(__float2half(acc[mi][nj][2]));
                smu.st[cc + 1][r + 8] = __half_as_ushort(__float2half(acc[mi][nj][3]));
            }
        }
        __syncthreads();
        int row = tid >> 1, ub = (tid & 1) * 8;
#pragma unroll
        for (int j = 0; j < 8; j++) {
            *(uint4*)&dst[(size_t)(tBase + row) * NC + oBase + (ub + j) * 8] =
                *(const uint4*)&smu.st[row][(ub + j) * 8];
        }
    }
}

// ============ Kernel 2: fused attention — 512 threads, QT=32, CH=64, monolithic ============
// smem (218368 B): Q [8h][32q][72] | KV: K [8h][64t][72] / V [512c][72t] overlay |
// S [8h][32q][68] f32 | P [8g][32q][72] half | Scs [8g][32q] f32 | whs 64 f32
// 16 warps: QK warp (h, khalf) does S_h T-half; PV warp (g, khalf) does d-half.
__global__ __launch_bounds__(512) void fa6(const float* __restrict__ w_head) {
    extern __shared__ char smc[];
    __half* QsH = (__half*)smc;
    __half* KVH = (__half*)(smc + 36864);
    float*  SsF = (float*)(smc + 110592);
    __half* PsH = (__half*)(smc + 180224);
    float*  Scs = (float*)(smc + 217088);
    float*  whs = (float*)(smc + 218112);
    uint32_t* QsU = (uint32_t*)QsH;
    uint32_t* KVU = (uint32_t*)KVH;
    uint32_t* PsU = (uint32_t*)PsH;

    int b = blockIdx.y;
    int qBase = blockIdx.x * QT;
    int tid = threadIdx.x, lane = tid & 31, wid = tid >> 5;
    int h8 = wid & 7, khalf = wid >> 3;
    int lr = lane >> 2, lk = lane & 3;
    int q32 = tid >> 4, pos16 = tid & 15;   // D-phase: 32 q x 16 threads x 4 T

    if (tid < 64) whs[tid] = w_head[tid] * 1.4426950408889634f;

    // stage Q [8h][32q][72], pre-scaled by 0.125 (exact in fp16)
    {
        const __half* Qsrc = g_qT + ((size_t)b * NT + qBase) * NC;
        __half2 sc8 = __float2half2_rn(0.125f);
#pragma unroll
        for (int i = 0; i < 4; i++) {
            int idx = tid + i * 512;
            int u3 = idx & 7, q = (idx >> 3) & 31, h = idx >> 8;
            uint4 v = *(const uint4*)&Qsrc[q * NC + h * 64 + u3 * 8];
            __half2* p2 = (__half2*)&v;
            p2[0] = __hmul2(p2[0], sc8); p2[1] = __hmul2(p2[1], sc8);
            p2[2] = __hmul2(p2[2], sc8); p2[3] = __hmul2(p2[3], sc8);
            *(uint4*)&QsH[h * 2304 + q * 72 + u3 * 8] = v;
        }
    }

    float m[8], l[8], s2[8];
#pragma unroll
    for (int g = 0; g < 8; g++) { m[g] = -1e30f; l[g] = 0.f; s2[g] = 0.f; }

    float pv[2][4][4];   // warp (g, khalf): 32q x d-half (nj tiles khalf*4..+4)
#pragma unroll
    for (int mi = 0; mi < 2; mi++)
#pragma unroll
        for (int nj = 0; nj < 4; nj++)
#pragma unroll
            for (int ci = 0; ci < 4; ci++) pv[mi][nj][ci] = 0.f;

    const __half* Ksrc = g_kT + (size_t)b * NT * NC;
    const __half* Vsrc = g_vh + (size_t)b * NC * NT;

    __syncthreads();

    for (int c0 = 0; c0 < NT; c0 += CH) {
        // ---- A: stage K [8h][64t][72] ----
#pragma unroll
        for (int i = 0; i < 8; i++) {
            int idx = tid + i * 512;
            int u3 = idx & 7, t = (idx >> 3) & 63, h = idx >> 9;
            uint4 v = *(const uint4*)&Ksrc[(size_t)(c0 + t) * NC + h * 64 + u3 * 8];
            *(uint4*)&KVH[h * 4608 + t * 72 + u3 * 8] = v;
        }
        __syncthreads();

        // ---- B: warp (h, khalf) computes S_h[32q][khalf-T-half] -> fp32 smem ----
        {
            float sacc[2][4][4];
#pragma unroll
            for (int mi = 0; mi < 2; mi++)
#pragma unroll
                for (int nj = 0; nj < 4; nj++)
#pragma unroll
                    for (int ci = 0; ci < 4; ci++) sacc[mi][nj][ci] = 0.f;
#pragma unroll
            for (int ks = 0; ks < 4; ks++) {
                int kb = ks * 8;
                uint32_t af[2][4], bf[4][2];
#pragma unroll
                for (int mi = 0; mi < 2; mi++) {
                    int m0 = mi * 16 + lr;
                    af[mi][0] = QsU[h8 * 1152 + m0 * 36 + kb + lk];
                    af[mi][1] = QsU[h8 * 1152 + (m0 + 8) * 36 + kb + lk];
                    af[mi][2] = QsU[h8 * 1152 + m0 * 36 + kb + lk + 4];
                    af[mi][3] = QsU[h8 * 1152 + (m0 + 8) * 36 + kb + lk + 4];
                }
#pragma unroll
                for (int nj = 0; nj < 4; nj++) {
                    int n0 = khalf * 32 + nj * 8 + lr;
                    bf[nj][0] = KVU[h8 * 2304 + n0 * 36 + kb + lk];
                    bf[nj][1] = KVU[h8 * 2304 + n0 * 36 + kb + lk + 4];
                }
#pragma unroll
                for (int mi = 0; mi < 2; mi++)
#pragma unroll
                    for (int nj = 0; nj < 4; nj++) mma16h(sacc[mi][nj], af[mi], bf[nj]);
            }
            float* Sh = SsF + h8 * 2176 + khalf * 32;
#pragma unroll
            for (int mi = 0; mi < 2; mi++) {
                int r0 = mi * 16 + lr;
#pragma unroll
                for (int nj = 0; nj < 4; nj++) {
                    int cc = nj * 8 + lk * 2;
                    *(float2*)&Sh[r0 * 68 + cc] = make_float2(sacc[mi][nj][0], sacc[mi][nj][1]);
                    *(float2*)&Sh[(r0 + 8) * 68 + cc] = make_float2(sacc[mi][nj][2], sacc[mi][nj][3]);
                }
            }
        }
        __syncthreads();

        // ---- D: mix (f32x2) + base-2 online softmax -> P fp16 ----
        {
            unsigned long long xh[16];
            const float* Sq = SsF + q32 * 68 + pos16 * 4;
#pragma unroll
            for (int h = 0; h < 8; h++) {
                xh[h * 2]     = __double_as_longlong(*(const double*)(Sq + h * 2176));
                xh[h * 2 + 1] = __double_as_longlong(*(const double*)(Sq + h * 2176 + 2));
            }
#pragma unroll
            for (int g = 0; g < 8; g++) {
                unsigned long long a0 = 0, a1 = 0;
#pragma unroll
                for (int h = 0; h < 8; h++) {
                    float w = whs[g * 8 + h];
                    unsigned long long w2;
                    asm("mov.b64 %0, {%1, %1};" : "=l"(w2) : "f"(w));
                    asm("fma.rn.f32x2 %0, %1, %2, %0;" : "+l"(a0) : "l"(w2), "l"(xh[h * 2]));
                    asm("fma.rn.f32x2 %0, %1, %2, %0;" : "+l"(a1) : "l"(w2), "l"(xh[h * 2 + 1]));
                }
                float mg0, mg1, mg2, mg3;
                asm("mov.b64 {%0, %1}, %2;" : "=f"(mg0), "=f"(mg1) : "l"(a0));
                asm("mov.b64 {%0, %1}, %2;" : "=f"(mg2), "=f"(mg3) : "l"(a1));

                float cm = fmaxf(fmaxf(mg0, mg1), fmaxf(mg2, mg3));
                cm = fmaxf(cm, __shfl_xor_sync(0xffffffffu, cm, 1));
                cm = fmaxf(cm, __shfl_xor_sync(0xffffffffu, cm, 2));
                cm = fmaxf(cm, __shfl_xor_sync(0xffffffffu, cm, 4));
                cm = fmaxf(cm, __shfl_xor_sync(0xffffffffu, cm, 8));
                float nm = fmaxf(m[g], cm);
                float sc = ex2f(m[g] - nm);
                m[g] = nm;
                float e0 = ex2f(mg0 - nm), e1 = ex2f(mg1 - nm);
                float e2 = ex2f(mg2 - nm), e3 = ex2f(mg3 - nm);
                float cl = (e0 + e1) + (e2 + e3);
                float cq = (e0 * e0 + e1 * e1) + (e2 * e2 + e3 * e3);
                cl += __shfl_xor_sync(0xffffffffu, cl, 1);
                cq += __shfl_xor_sync(0xffffffffu, cq, 1);
                cl += __shfl_xor_sync(0xffffffffu, cl, 2);
                cq += __shfl_xor_sync(0xffffffffu, cq, 2);
                cl += __shfl_xor_sync(0xffffffffu, cl, 4);
                cq += __shfl_xor_sync(0xffffffffu, cq, 4);
                cl += __shfl_xor_sync(0xffffffffu, cl, 8);
                cq += __shfl_xor_sync(0xffffffffu, cq, 8);
                l[g] = l[g] * sc + cl;
                s2[g] = s2[g] * (sc * sc) + cq;
                __half2 p0 = __floats2half2_rn(e0, e1);
                __half2 p1 = __floats2half2_rn(e2, e3);
                uint2 u;
                u.x = *(uint32_t*)&p0; u.y = *(uint32_t*)&p1;
                *(uint2*)&PsU[g * 1152 + q32 * 36 + pos16 * 2] = u;
                if (pos16 == 0) Scs[g * 32 + q32] = sc;
            }
        }
        // ---- E: stage V [512c][72t] over K region ----
#pragma unroll
        for (int i = 0; i < 8; i++) {
            int idx = tid + i * 512;
            int c = idx >> 3, seg = idx & 7;
            uint4 v = *(const uint4*)&Vsrc[(size_t)c * NT + c0 + seg * 8];
            *(uint4*)&KVH[c * 72 + seg * 8] = v;
        }
        __syncthreads();

        // ---- F: warp (g, khalf) accumulates P_g @ V_g^T for its d-half ----
        {
            int g = h8;
            float s00 = Scs[g * 32 + lr],      s01 = Scs[g * 32 + lr + 8];
            float s10 = Scs[g * 32 + 16 + lr], s11 = Scs[g * 32 + 24 + lr];
#pragma unroll
            for (int nj = 0; nj < 4; nj++) {
                pv[0][nj][0] *= s00; pv[0][nj][1] *= s00;
                pv[0][nj][2] *= s01; pv[0][nj][3] *= s01;
                pv[1][nj][0] *= s10; pv[1][nj][1] *= s10;
                pv[1][nj][2] *= s11; pv[1][nj][3] *= s11;
            }
#pragma unroll
            for (int kt = 0; kt < 4; kt++) {
                int kb = kt * 8;
                uint32_t af[2][4], bf[4][2];
#pragma unroll
                for (int mi = 0; mi < 2; mi++) {
                    int m0 = mi * 16 + lr;
                    af[mi][0] = PsU[g * 1152 + m0 * 36 + kb + lk];
                    af[mi][1] = PsU[g * 1152 + (m0 + 8) * 36 + kb + lk];
                    af[mi][2] = PsU[g * 1152 + m0 * 36 + kb + lk + 4];
                    af[mi][3] = PsU[g * 1152 + (m0 + 8) * 36 + kb + lk + 4];
                }
#pragma unroll
                for (int nj = 0; nj < 4; nj++) {
                    int c = g * 64 + khalf * 32 + nj * 8 + lr;
                    bf[nj][0] = KVU[c * 36 + kb + lk];
                    bf[nj][1] = KVU[c * 36 + kb + lk + 4];
                }
#pragma unroll
                for (int mi = 0; mi < 2; mi++)
#pragma unroll
                    for (int nj = 0; nj < 4; nj++) mma16h(pv[mi][nj], af[mi], bf[nj]);
            }
        }
        __syncthreads();
    }

    // ---- epilogue: stats + O (disjoint d-halves, direct store) ----
    if (pos16 == 0) {
#pragma unroll
        for (int g = 0; g < 8; g++) {
            int r = (b * 8 + g) * NT + qBase + q32;
            g_l[r] = l[g];
            g_rowsq[r] = s2[g] / (l[g] * l[g]);
        }
    }
    {
        int g = h8;
        float* Op = g_oacc + ((size_t)(b * 8 + g) * NT + qBase) * NHD + khalf * 32;
#pragma unroll
        for (int mi = 0; mi < 2; mi++) {
            int r0 = mi * 16 + lr;
#pragma unroll
            for (int nj = 0; nj < 4; nj++) {
                int cc = nj * 8 + lk * 2;
                *(float2*)&Op[(size_t)r0 * NHD + cc] = make_float2(pv[mi][nj][0], pv[mi][nj][1]);
                *(float2*)&Op[(size_t)(r0 + 8) * NHD + cc] = make_float2(pv[mi][nj][2], pv[mi][nj][3]);
            }
        }
    }
}

// ============ Kernel 4: vsum — one warp per row, MLP 4 ============
__global__ __launch_bounds__(256) void vsum2() {
    int wid = threadIdx.x >> 5, lane = threadIdx.x & 31;
    int row = blockIdx.x * 8 + wid;
    const uint4* p = (const uint4*)(g_vh + (size_t)row * NT);
    uint4 u0 = p[lane], u1 = p[lane + 32], u2 = p[lane + 64], u3 = p[lane + 96];
    float s = 0.f;
#pragma unroll
    for (int k = 0; k < 4; k++) {
        uint4 u = (k == 0) ? u0 : (k == 1) ? u1 : (k == 2) ? u2 : u3;
        const __half2* h2 = (const __half2*)&u;
#pragma unroll
        for (int j = 0; j < 4; j++) {
            float2 f = __half22float2(h2[j]);
            s += f.x + f.y;
        }
    }
#pragma unroll
    for (int o = 16; o > 0; o >>= 1) s += __shfl_xor_sync(0xffffffffu, s, o);
    if (lane == 0) g_vsum[row] = s;
}

// ============ Kernel 5: finalize InstanceNorm params ============
__global__ __launch_bounds__(256) void finalize_kernel(const float* __restrict__ gamma,
                                                       const float* __restrict__ beta) {
    __shared__ float sbuf[8];
    int grp = blockIdx.x;
    float s = 0.f;
    for (int i = threadIdx.x; i < NT; i += 256) s += g_rowsq[grp * NT + i];
    int lane = threadIdx.x & 31, w = threadIdx.x >> 5;
#pragma unroll
    for (int o = 16; o > 0; o >>= 1) s += __shfl_xor_sync(0xffffffffu, s, o);
    if (lane == 0) sbuf[w] = s;
    __syncthreads();
    if (threadIdx.x == 0) {
        float sumsq = 0.f;
        for (int i = 0; i < 8; i++) sumsq += sbuf[i];
        const float invN = 1.f / (1024.f * 1024.f);
        float mean = 1.f / 1024.f;
        float var = sumsq * invN - mean * mean;
        int h = grp & 7;
        float alpha = gamma[h] * rsqrtf(var + EPS_IN);
        g_alpha[grp] = alpha;
        g_betac[grp] = beta[h] - alpha * mean;
    }
}

// ============ Kernel 6: projection with fused normalize epilogue-on-load ============
// mid flat t*512+c: h = t>>7, q = (t&127)*8 + (c>>6), d = c&63.
__global__ __launch_bounds__(256) void proj_fused(const float* __restrict__ b_proj,
                                                  float* __restrict__ outF) {
    int b = blockIdx.z;
    int coBase = blockIdx.y * 128;
    int tBase = blockIdx.x * 128;
    const __half* W = g_w16 + (size_t)3 * NC * NC;

    __shared__ uint32_t As[128][20];
    __shared__ uint32_t Bs[128][20];

    int tid = threadIdx.x, lane = tid & 31, wid = tid >> 5;
    int wm = wid >> 2, wn = wid & 3;
    int lr = lane >> 2, lk = lane & 3;

    float acc[4][4][4];
#pragma unroll
    for (int mi = 0; mi < 4; mi++)
#pragma unroll
        for (int nj = 0; nj < 4; nj++)
#pragma unroll
            for (int ci = 0; ci < 4; ci++) acc[mi][nj][ci] = 0.f;

    for (int k0 = 0; k0 < NC; k0 += 32) {
        int chi = k0 >> 6;
        int dBase = k0 & 63;
#pragma unroll
        for (int i = 0; i < 2; i++) {
            int idx = tid + i * 256;
            int row = idx >> 2, uu = idx & 3;
            *(uint4*)&As[row][uu * 4] =
                *(const uint4*)&W[(size_t)(coBase + row) * NC + k0 + uu * 8];
            int t = tBase + row;
            int bh = b * 8 + (t >> 7);
            int q  = ((t & 127) << 3) + chi;
            int d0 = dBase + uu * 8;
            float alpha = g_alpha[bh], bc = g_betac[bh];
            const float* Op = &g_oacc[((size_t)bh * NT + q) * NHD + d0];
            float4 o0 = *(const float4*)Op;
            float4 o1 = *(const float4*)(Op + 4);
            float ail = alpha / g_l[bh * NT + q];
            float4 v0 = *(const float4*)&g_vsum[bh * NHD + d0];
            float4 v1 = *(const float4*)&g_vsum[bh * NHD + d0 + 4];
            __half2 h0 = __floats2half2_rn(ail * o0.x + bc * v0.x, ail * o0.y + bc * v0.y);
            __half2 h1 = __floats2half2_rn(ail * o0.z + bc * v0.z, ail * o0.w + bc * v0.w);
            __half2 h2 = __floats2half2_rn(ail * o1.x + bc * v1.x, ail * o1.y + bc * v1.y);
            __half2 h3 = __floats2half2_rn(ail * o1.z + bc * v1.z, ail * o1.w + bc * v1.w);
            uint4 u;
            u.x = *(uint32_t*)&h0; u.y = *(uint32_t*)&h1;
            u.z = *(uint32_t*)&h2; u.w = *(uint32_t*)&h3;
            *(uint4*)&Bs[row][uu * 4] = u;
        }
        __syncthreads();
#pragma unroll
        for (int ci = 0; ci < 2; ci++) {
            int kc = ci * 8;
            uint32_t af[4][4], bf[4][2];
#pragma unroll
            for (int mi = 0; mi < 4; mi++) {
                int m0 = wm * 64 + mi * 16 + lr;
                af[mi][0] = As[m0][kc + lk];
                af[mi][1] = As[m0 + 8][kc + lk];
                af[mi][2] = As[m0][kc + lk + 4];
                af[mi][3] = As[m0 + 8][kc + lk + 4];
            }
#pragma unroll
            for (int nj = 0; nj < 4; nj++) {
                int n0 = wn * 32 + nj * 8 + lr;
                bf[nj][0] = Bs[n0][kc + lk];
                bf[nj][1] = Bs[n0][kc + lk + 4];
            }
#pragma unroll
            for (int mi = 0; mi < 4; mi++)
#pragma unroll
                for (int nj = 0; nj < 4; nj++) mma16h(acc[mi][nj], af[mi], bf[nj]);
        }
        __syncthreads();
    }
#pragma unroll
    for (int mi = 0; mi < 4; mi++) {
        int co = coBase + wm * 64 + mi * 16 + lr;
        float bias0 = b_proj[co], bias1 = b_proj[co + 8];
        float* op0 = outF + (size_t)b * NC * NT + (size_t)co * NT;
        float* op1 = op0 + (size_t)8 * NT;
#pragma unroll
        for (int nj = 0; nj < 4; nj++) {
            int cc = tBase + wn * 32 + nj * 8 + lk * 2;
            *(float2*)&op0[cc] = make_float2(acc[mi][nj][0] + bias0, acc[mi][nj][1] + bias0);
            *(float2*)&op1[cc] = make_float2(acc[mi][nj][2] + bias1, acc[mi][nj][3] + bias1);
        }
    }
}

// ---------------- launch ----------------
extern "C" void kernel_launch(void* const* d_in, const int* in_sizes, int n_in,
                              void* d_out, int out_size) {
    (void)in_sizes; (void)n_in; (void)out_size;
    const float* x        = (const float*)d_in[0];
    const float* w_q      = (const float*)d_in[1];
    const float* w_k      = (const float*)d_in[2];
    const float* w_v      = (const float*)d_in[3];
    const float* w_head   = (const float*)d_in[4];
    const float* in_gamma = (const float*)d_in[5];
    const float* in_beta  = (const float*)d_in[6];
    const float* w_proj   = (const float*)d_in[7];
    const float* b_proj   = (const float*)d_in[8];
    float* outF = (float*)d_out;

    const int FA_SMEM = 218368;
    cudaFuncSetAttribute(fa6, cudaFuncAttributeMaxDynamicSharedMemorySize, FA_SMEM);

    prep_w<<<4096, 256>>>(w_q, w_k, w_v, w_proj);
    prep_x<<<dim3(32, 16, 4), dim3(32, 8)>>>(x);
    qkv_f16<<<dim3(8, 4, 12), 256>>>();
    fa6<<<dim3(NT / QT, NB), 512, FA_SMEM>>>(w_head);     // 4th launch -> ncu target
    vsum2<<<256, 256>>>();
    finalize_kernel<<<32, 256>>>(in_gamma, in_beta);
    proj_fused<<<dim3(8, 4, 4), 256>>>(b_proj, outF);
}